// round 16
// baseline (speedup 1.0000x reference)
#include <cuda_runtime.h>
#include <cuda_fp16.h>
#include <math.h>
#include <stdint.h>

// ============================================================
// QGRUCell via mma.sync (HMMA fp16) — sm_103-baseline ISA only.
// R16: 128-thread CTAs, tile 64x32 -> 4 CTAs/SM (RF 4*128*128 =
// 64K exactly; smem 4*40KB=160KB). Same 16 warps/SM as R15 but
// 4 independent barrier domains -> deeper stall hiding; tail
// quanta halve. fp16 1-term (rel_err 2.494e-4) retained.
// ============================================================

#define BATCH   8192
#define KDIM    512
#define M_TILE  64
#define N_TILE  32
#define KC      64              // fp16 per chunk = 128B rows
#define CHUNKS  16              // 8 x-chunks + 8 h-chunks

// smem stage: A [64x128B] + 3 gate B tiles [32x128B]
#define OFFA     0
#define OFFB(g)  (8192 + (g) * 4096)
#define STAGE_B  20480
#define NSTAGES  2
#define SMEM_TOTAL (NSTAGES * STAGE_B)   // 40960 (x4 CTAs = 160KB)

// ---- fp16 scratch ----
__device__ __align__(16) __half g_xh[BATCH * KDIM];
__device__ __align__(16) __half g_hh[BATCH * KDIM];
__device__ __align__(16) __half g_wih_h[3 * KDIM * KDIM];
__device__ __align__(16) __half g_whh_h[3 * KDIM * KDIM];

// ---- baseline-ISA helpers ----
__device__ __forceinline__ uint32_t smem_u32(const void* p) {
    uint32_t a;
    asm("{ .reg .u64 t; cvta.to.shared.u64 t, %1; cvt.u32.u64 %0, t; }"
        : "=r"(a) : "l"(p));
    return a;
}
__device__ __forceinline__ void cp16(uint32_t s, const void* g) {
    asm volatile("cp.async.cg.shared.global [%0], [%1], 16;"
                 :: "r"(s), "l"(g));
}
#define CP_COMMIT() asm volatile("cp.async.commit_group;" ::: "memory")
#define CP_WAIT(n)  asm volatile("cp.async.wait_group %0;" :: "n"(n) : "memory")

__device__ __forceinline__ void ldsm4(uint32_t* r, uint32_t addr) {
    asm volatile("ldmatrix.sync.aligned.m8n8.x4.shared.b16 {%0,%1,%2,%3}, [%4];"
                 : "=r"(r[0]), "=r"(r[1]), "=r"(r[2]), "=r"(r[3])
                 : "r"(addr));
}
__device__ __forceinline__ void mma16816(float* c, const uint32_t* a,
                                         const uint32_t* b) {
    asm volatile(
        "mma.sync.aligned.m16n8k16.row.col.f32.f16.f16.f32 "
        "{%0,%1,%2,%3}, {%4,%5,%6,%7}, {%8,%9}, {%0,%1,%2,%3};"
        : "+f"(c[0]), "+f"(c[1]), "+f"(c[2]), "+f"(c[3])
        : "r"(a[0]), "r"(a[1]), "r"(a[2]), "r"(a[3]), "r"(b[0]), "r"(b[1]));
}

// ---- quant helpers ----
__device__ __forceinline__ float qround(float x, float s, float is) {
    return floorf(__fadd_rn(__fmul_rn(x, s), 0.5f)) * is;
}
#define Q14F  16384.0f
#define IQ14F 6.103515625e-5f
#define Q15F  32768.0f
#define IQ15F 3.0517578125e-5f
#define Q27F  1.34217728e8f
#define IQ27F 7.450580596923828e-9f
#define Q31F  2.147483648e9f
#define IQ16F 1.52587890625e-5f

__device__ __forceinline__ float qsigmoid_dev(float x) {
    float i = floorf(__fadd_rn(__fmul_rn(x, Q27F), 0.5f));
    i = fminf(fmaxf(i, -2.147483648e9f), 2.147483648e9f);
    float s = 1.0f / (1.0f + expf(-i * IQ27F));
    float o31 = floorf(__fadd_rn(__fmul_rn(s, Q31F), 0.5f));
    float o15 = floorf(__fadd_rn(__fmul_rn(o31, IQ16F), 0.5f));
    return o15 * IQ15F;
}
__device__ __forceinline__ float qtanh_dev(float x) {
    float i = floorf(__fadd_rn(__fmul_rn(x, Q27F), 0.5f));
    i = fminf(fmaxf(i, -2.147483648e9f), 2.147483648e9f);
    float t = tanhf(i * IQ27F);
    float o31 = floorf(__fadd_rn(__fmul_rn(t, Q31F), 0.5f));
    float o15 = floorf(__fadd_rn(__fmul_rn(o31, IQ16F), 0.5f));
    return o15 * IQ15F;
}

// ============================================================
// Kernel 1: round x, h, Wih, Whh to fp16
// ============================================================
#define NX4 (BATCH * KDIM / 4)
#define NW4 (3 * KDIM * KDIM / 4)
#define TOT4 (2 * NX4 + 2 * NW4)

__global__ void cvt4_kernel(const float* __restrict__ x,
                            const float* __restrict__ h,
                            const float* __restrict__ wih,
                            const float* __restrict__ whh) {
    size_t i = (size_t)blockIdx.x * 256 + threadIdx.x;
    const float* src;
    __half* dst;
    size_t j;
    if (i < NX4)                { src = x;   dst = g_xh;    j = i; }
    else if (i < 2 * NX4)       { src = h;   dst = g_hh;    j = i - NX4; }
    else if (i < 2 * NX4 + NW4) { src = wih; dst = g_wih_h; j = i - 2 * NX4; }
    else                        { src = whh; dst = g_whh_h; j = i - 2 * NX4 - NW4; }

    float4 v = reinterpret_cast<const float4*>(src)[j];
    __half2 p0 = __halves2half2(__float2half_rn(v.x), __float2half_rn(v.y));
    __half2 p1 = __halves2half2(__float2half_rn(v.z), __float2half_rn(v.w));
    reinterpret_cast<__half2*>(dst)[2 * j]     = p0;
    reinterpret_cast<__half2*>(dst)[2 * j + 1] = p1;
}

// ============================================================
// Kernel 2: fused HMMA GEMMs + quantized GRU epilogue
// ============================================================

// Stage loader: 128 threads x 10 cp16 = 20KB.
__device__ __forceinline__ void load_stage(
    uint32_t stb, int chunk, int m0, int n0, int tid)
{
    const int phase = (chunk >= 8);
    const int k0 = (chunk & 7) * KC;

    const __half* ap = phase ? g_hh : g_xh;
    const __half* wp = phase ? g_whh_h : g_wih_h;

    // A: row = tid>>1 (0..63), four segs c0..c0+3
    {
        const int row = tid >> 1;
        const int c0 = (tid & 1) * 4;
        const int sw = row & 7;
        const uint32_t rbase = stb + OFFA + row * 128;
        const size_t aoff = (size_t)(m0 + row) * KDIM + k0;
        #pragma unroll
        for (int s = 0; s < 4; ++s)
            cp16(rbase + (((c0 + s) ^ sw) << 4), ap + aoff + (c0 + s) * 8);
    }
    // B: rows q*16 + (tid>>3), seg c = tid&7; 2 rows x 3 gates
    {
        const int r0 = tid >> 3;        // 0..15
        const int c = tid & 7;
        #pragma unroll
        for (int q = 0; q < 2; ++q) {
            const int row = q * 16 + r0;
            const int sw = row & 7;
            const uint32_t rb = stb + row * 128 + (((c ^ sw)) << 4);
            const size_t goff = (size_t)(n0 + row) * KDIM + k0 + c * 8;
            #pragma unroll
            for (int g = 0; g < 3; ++g)
                cp16(rb + OFFB(g), wp + goff + (size_t)g * KDIM * KDIM);
        }
    }
}

// Warp tile 32x16. Per k-step: 5 LDSMs batched, 12 independent MMAs.
__device__ __forceinline__ void compute_chunk(
    uint32_t stb,
    float accR[4][4], float accI[4][4], float accN[4][4],
    uint32_t aRowB0, int aSw, int aCk,
    uint32_t bRowB, int bSw, int bCk)
{
    #pragma unroll
    for (int ks = 0; ks < 4; ++ks) {
        uint32_t af[2][4], bf[3][4];
        const uint32_t asel = (uint32_t)(((2 * ks + aCk) ^ aSw)) << 4;
        const uint32_t bsel = bRowB + ((uint32_t)((2 * ks + bCk) ^ bSw) << 4);

        ldsm4(af[0], stb + OFFA + aRowB0 + asel);
        ldsm4(af[1], stb + OFFA + aRowB0 + 16 * 128 + asel);
        #pragma unroll
        for (int g = 0; g < 3; ++g)
            ldsm4(bf[g], stb + OFFB(g) + bsel);

        #pragma unroll
        for (int g = 0; g < 3; ++g) {
            float (*acc)[4] = (g == 0) ? accR : (g == 1) ? accI : accN;
            #pragma unroll
            for (int rh = 0; rh < 2; ++rh) {
                mma16816(acc[rh * 2 + 0], af[rh], bf[g] + 0);
                mma16816(acc[rh * 2 + 1], af[rh], bf[g] + 2);
            }
        }
    }
}

__global__ __launch_bounds__(128, 4) void qgru_mma_kernel(
    const float* __restrict__ h_in,
    const float* __restrict__ bih,
    const float* __restrict__ bhh,
    float* __restrict__ out)
{
    extern __shared__ __align__(1024) char smem[];
    const uint32_t sb = smem_u32(smem);
    const int tid  = threadIdx.x;
    const int wid  = tid >> 5;
    const int lane = tid & 31;
    const int m0 = blockIdx.y * M_TILE;
    const int n0 = blockIdx.x * N_TILE;

    const int wm = wid & 1;         // 2 M-warps: 32 rows each
    const int wn = wid >> 1;        // 2 N-warps: 16 cols each

    // ldmatrix lane geometry
    const int aRow = wm * 32 + (lane & 15);
    const uint32_t aRowB0 = (uint32_t)aRow * 128;
    const int aSw = aRow & 7;
    const int aCk = lane >> 4;
    const int bRow = wn * 16 + (lane & 7) + ((lane >> 4) << 3);
    const uint32_t bRowB = (uint32_t)bRow * 128;
    const int bSw = bRow & 7;
    const int bCk = (lane >> 3) & 1;

    float accR[4][4], accI[4][4], accNi[4][4], accNh[4][4];
    #pragma unroll
    for (int s = 0; s < 4; ++s)
        #pragma unroll
        for (int r = 0; r < 4; ++r) {
            accR[s][r] = 0.f; accI[s][r] = 0.f;
            accNi[s][r] = 0.f; accNh[s][r] = 0.f;
        }

    // ---- single-sync 2-stage pipeline (R12-validated pattern) ----
    load_stage(sb, 0, m0, n0, tid);
    CP_COMMIT();

    #pragma unroll 1
    for (int c = 0; c < CHUNKS; ++c) {
        CP_WAIT(0);            // load(c) complete
        __syncthreads();       // all warps done with compute(c-1):
                               // buffer (c+1)&1 is free to overwrite
        if (c + 1 < CHUNKS) {
            load_stage(sb + ((c + 1) & 1) * STAGE_B, c + 1, m0, n0, tid);
            CP_COMMIT();
        }
        const uint32_t stb = sb + (c & 1) * STAGE_B;
        if (c < 8)
            compute_chunk(stb, accR, accI, accNi, aRowB0, aSw, aCk, bRowB, bSw, bCk);
        else
            compute_chunk(stb, accR, accI, accNh, aRowB0, aSw, aCk, bRowB, bSw, bCk);
    }

    // ---- fused quantized GRU epilogue ----
    const int l4 = lane >> 2;
    const int lm = lane & 3;

    #pragma unroll
    for (int pos = 0; pos < 4; ++pos) {
        const int rh = pos >> 1;
        const int nh = pos & 1;
        const int col = n0 + wn * 16 + nh * 8 + lm * 2;
        const float br0 = __ldg(bih + col)     + __ldg(bhh + col);
        const float br1 = __ldg(bih + col + 1) + __ldg(bhh + col + 1);
        const float bi0 = __ldg(bih + 512 + col)     + __ldg(bhh + 512 + col);
        const float bi1 = __ldg(bih + 512 + col + 1) + __ldg(bhh + 512 + col + 1);
        const float bni0 = __ldg(bih + 1024 + col);
        const float bni1 = __ldg(bih + 1024 + col + 1);
        const float bnh0 = __ldg(bhh + 1024 + col);
        const float bnh1 = __ldg(bhh + 1024 + col + 1);

        #pragma unroll
        for (int half = 0; half < 2; ++half) {
            const int row = m0 + wm * 32 + rh * 16 + l4 + half * 8;
            const float2 hv = *reinterpret_cast<const float2*>(
                h_in + (size_t)row * KDIM + col);
            float res[2];
            #pragma unroll
            for (int e = 0; e < 2; ++e) {
                const int r = half * 2 + e;
                const float rsum = accR[pos][r] + (e ? br1 : br0);
                const float isum = accI[pos][r] + (e ? bi1 : bi0);
                const float gin  = qround(accNi[pos][r] + (e ? bni1 : bni0),
                                          Q14F, IQ14F);
                const float ghn  = qround(accNh[pos][r] + (e ? bnh1 : bnh0),
                                          Q14F, IQ14F);
                const float resetg = qsigmoid_dev(rsum);
                const float inputg = qsigmoid_dev(isum);
                const float rhn  = qround(__fmul_rn(resetg, ghn), Q15F, IQ15F);
                const float newg = qtanh_dev(rhn + gin);
                const float nh2  = qround(e ? hv.y : hv.x, Q15F, IQ15F);
                res[e] = __fadd_rn(newg,
                                   __fmul_rn(inputg, __fsub_rn(nh2, newg)));
            }
            float2 o; o.x = res[0]; o.y = res[1];
            *reinterpret_cast<float2*>(out + (size_t)row * KDIM + col) = o;
        }
    }
}

extern "C" void kernel_launch(void* const* d_in, const int* in_sizes, int n_in,
                              void* d_out, int out_size) {
    const float* x   = (const float*)d_in[0];  // [8192, 512]
    const float* h   = (const float*)d_in[1];  // [8192, 512]
    const float* wih = (const float*)d_in[2];  // [1536, 512]
    const float* whh = (const float*)d_in[3];  // [1536, 512]
    const float* bih = (const float*)d_in[4];  // [1536]
    const float* bhh = (const float*)d_in[5];  // [1536]
    float* out = (float*)d_out;                // [8192, 512]

    cvt4_kernel<<<TOT4 / 256, 256>>>(x, h, wih, whh);

    cudaFuncSetAttribute(qgru_mma_kernel,
                         cudaFuncAttributeMaxDynamicSharedMemorySize, SMEM_TOTAL);
    dim3 grid(KDIM / N_TILE, BATCH / M_TILE);  // (16, 128) = 2048 CTAs
    qgru_mma_kernel<<<grid, 128, SMEM_TOTAL>>>(h, bih, bhh, out);
}

// round 17
// speedup vs baseline: 1.0215x; 1.0215x over previous
#include <cuda_runtime.h>
#include <cuda_fp16.h>
#include <math.h>
#include <stdint.h>

// ============================================================
// QGRUCell via mma.sync (HMMA fp16) — sm_103-baseline ISA only.
// R17 = R15 config (M64xN64, 256thr, 2 CTAs/SM, 3-stage cp.async,
// fp16 1-term) + intra-chunk fragment PING-PONG: frags(ks+1)
// loaded before MMAs(ks) so LDSM (crossbar) and HMMA (tensor)
// issue concurrently instead of phase-alternating (R15 showed
// tensor=47% / L1=48% anti-correlated halves).
// ============================================================

#define BATCH   8192
#define KDIM    512
#define M_TILE  64
#define N_TILE  64
#define KC      64              // fp16 per chunk = 128B rows
#define CHUNKS  16              // 8 x-chunks + 8 h-chunks

// smem stage: A [64x128B] + 3 gate B tiles [64x128B]
#define OFFA     0
#define OFFB(g)  (8192 + (g) * 8192)
#define STAGE_B  32768
#define NSTAGES  3
#define SMEM_TOTAL (NSTAGES * STAGE_B)   // 98304 (x2 CTAs = 192KB)

// ---- fp16 scratch ----
__device__ __align__(16) __half g_xh[BATCH * KDIM];
__device__ __align__(16) __half g_hh[BATCH * KDIM];
__device__ __align__(16) __half g_wih_h[3 * KDIM * KDIM];
__device__ __align__(16) __half g_whh_h[3 * KDIM * KDIM];

// ---- baseline-ISA helpers ----
__device__ __forceinline__ uint32_t smem_u32(const void* p) {
    uint32_t a;
    asm("{ .reg .u64 t; cvta.to.shared.u64 t, %1; cvt.u32.u64 %0, t; }"
        : "=r"(a) : "l"(p));
    return a;
}
__device__ __forceinline__ void cp16(uint32_t s, const void* g) {
    asm volatile("cp.async.cg.shared.global [%0], [%1], 16;"
                 :: "r"(s), "l"(g));
}
#define CP_COMMIT() asm volatile("cp.async.commit_group;" ::: "memory")
#define CP_WAIT(n)  asm volatile("cp.async.wait_group %0;" :: "n"(n) : "memory")

__device__ __forceinline__ void ldsm4(uint32_t* r, uint32_t addr) {
    asm volatile("ldmatrix.sync.aligned.m8n8.x4.shared.b16 {%0,%1,%2,%3}, [%4];"
                 : "=r"(r[0]), "=r"(r[1]), "=r"(r[2]), "=r"(r[3])
                 : "r"(addr));
}
__device__ __forceinline__ void mma16816(float* c, const uint32_t* a,
                                         const uint32_t* b) {
    asm volatile(
        "mma.sync.aligned.m16n8k16.row.col.f32.f16.f16.f32 "
        "{%0,%1,%2,%3}, {%4,%5,%6,%7}, {%8,%9}, {%0,%1,%2,%3};"
        : "+f"(c[0]), "+f"(c[1]), "+f"(c[2]), "+f"(c[3])
        : "r"(a[0]), "r"(a[1]), "r"(a[2]), "r"(a[3]), "r"(b[0]), "r"(b[1]));
}

// ---- quant helpers ----
__device__ __forceinline__ float qround(float x, float s, float is) {
    return floorf(__fadd_rn(__fmul_rn(x, s), 0.5f)) * is;
}
#define Q14F  16384.0f
#define IQ14F 6.103515625e-5f
#define Q15F  32768.0f
#define IQ15F 3.0517578125e-5f
#define Q27F  1.34217728e8f
#define IQ27F 7.450580596923828e-9f
#define Q31F  2.147483648e9f
#define IQ16F 1.52587890625e-5f

__device__ __forceinline__ float qsigmoid_dev(float x) {
    float i = floorf(__fadd_rn(__fmul_rn(x, Q27F), 0.5f));
    i = fminf(fmaxf(i, -2.147483648e9f), 2.147483648e9f);
    float s = 1.0f / (1.0f + expf(-i * IQ27F));
    float o31 = floorf(__fadd_rn(__fmul_rn(s, Q31F), 0.5f));
    float o15 = floorf(__fadd_rn(__fmul_rn(o31, IQ16F), 0.5f));
    return o15 * IQ15F;
}
__device__ __forceinline__ float qtanh_dev(float x) {
    float i = floorf(__fadd_rn(__fmul_rn(x, Q27F), 0.5f));
    i = fminf(fmaxf(i, -2.147483648e9f), 2.147483648e9f);
    float t = tanhf(i * IQ27F);
    float o31 = floorf(__fadd_rn(__fmul_rn(t, Q31F), 0.5f));
    float o15 = floorf(__fadd_rn(__fmul_rn(o31, IQ16F), 0.5f));
    return o15 * IQ15F;
}

// ============================================================
// Kernel 1: round x, h, Wih, Whh to fp16
// ============================================================
#define NX4 (BATCH * KDIM / 4)
#define NW4 (3 * KDIM * KDIM / 4)
#define TOT4 (2 * NX4 + 2 * NW4)

__global__ void cvt4_kernel(const float* __restrict__ x,
                            const float* __restrict__ h,
                            const float* __restrict__ wih,
                            const float* __restrict__ whh) {
    size_t i = (size_t)blockIdx.x * 256 + threadIdx.x;
    const float* src;
    __half* dst;
    size_t j;
    if (i < NX4)                { src = x;   dst = g_xh;    j = i; }
    else if (i < 2 * NX4)       { src = h;   dst = g_hh;    j = i - NX4; }
    else if (i < 2 * NX4 + NW4) { src = wih; dst = g_wih_h; j = i - 2 * NX4; }
    else                        { src = whh; dst = g_whh_h; j = i - 2 * NX4 - NW4; }

    float4 v = reinterpret_cast<const float4*>(src)[j];
    __half2 p0 = __halves2half2(__float2half_rn(v.x), __float2half_rn(v.y));
    __half2 p1 = __halves2half2(__float2half_rn(v.z), __float2half_rn(v.w));
    reinterpret_cast<__half2*>(dst)[2 * j]     = p0;
    reinterpret_cast<__half2*>(dst)[2 * j + 1] = p1;
}

// ============================================================
// Kernel 2: fused HMMA GEMMs + quantized GRU epilogue
// ============================================================

// Stage loader: 256 threads x 8 cp16 = 32KB.
__device__ __forceinline__ void load_stage(
    uint32_t stb, int chunk, int m0, int n0, int tid)
{
    const int phase = (chunk >= 8);
    const int k0 = (chunk & 7) * KC;

    const __half* ap = phase ? g_hh : g_xh;
    const __half* wp = phase ? g_whh_h : g_wih_h;

    // A: row = tid>>2 (0..63), two segs c0, c0+1
    {
        const int row = tid >> 2;
        const int c0 = (tid & 3) * 2;
        const int sw = row & 7;
        const uint32_t rbase = stb + OFFA + row * 128;
        const size_t aoff = (size_t)(m0 + row) * KDIM + k0;
        cp16(rbase + (((c0)     ^ sw) << 4), ap + aoff + (c0) * 8);
        cp16(rbase + (((c0 + 1) ^ sw) << 4), ap + aoff + (c0 + 1) * 8);
    }
    // B: rows q*32 + (tid>>3), seg c = tid&7; 2 rows x 3 gates
    {
        const int r0 = tid >> 3;        // 0..31
        const int c = tid & 7;
        #pragma unroll
        for (int q = 0; q < 2; ++q) {
            const int row = q * 32 + r0;
            const int sw = row & 7;
            const uint32_t rb = stb + row * 128 + (((c ^ sw)) << 4);
            const size_t goff = (size_t)(n0 + row) * KDIM + k0 + c * 8;
            #pragma unroll
            for (int g = 0; g < 3; ++g)
                cp16(rb + OFFB(g), wp + goff + (size_t)g * KDIM * KDIM);
        }
    }
}

// Fragment fetch for one k-step (5 LDSMs).
__device__ __forceinline__ void ld_frags(
    uint32_t stb, int ks,
    uint32_t af[2][4], uint32_t bf[3][4],
    uint32_t aRowB0, int aSw, int aCk,
    uint32_t bRowB, int bSw, int bCk)
{
    const uint32_t asel = (uint32_t)(((2 * ks + aCk) ^ aSw)) << 4;
    const uint32_t bsel = bRowB + ((uint32_t)((2 * ks + bCk) ^ bSw) << 4);
    ldsm4(af[0], stb + OFFA + aRowB0 + asel);
    ldsm4(af[1], stb + OFFA + aRowB0 + 16 * 128 + asel);
    #pragma unroll
    for (int g = 0; g < 3; ++g)
        ldsm4(bf[g], stb + OFFB(g) + bsel);
}

// Warp tile 32x16, PING-PONG fragments: frags(ks+1) are fetched
// before the 12 MMAs of ks, so LDSM and HMMA overlap in-warp.
__device__ __forceinline__ void compute_chunk(
    uint32_t stb,
    float accR[4][4], float accI[4][4], float accN[4][4],
    uint32_t aRowB0, int aSw, int aCk,
    uint32_t bRowB, int bSw, int bCk)
{
    uint32_t af[2][2][4], bf[2][3][4];
    ld_frags(stb, 0, af[0], bf[0], aRowB0, aSw, aCk, bRowB, bSw, bCk);

    #pragma unroll
    for (int ks = 0; ks < 4; ++ks) {
        const int cur = ks & 1;
        const int nxt = cur ^ 1;
        if (ks < 3)
            ld_frags(stb, ks + 1, af[nxt], bf[nxt],
                     aRowB0, aSw, aCk, bRowB, bSw, bCk);

        #pragma unroll
        for (int g = 0; g < 3; ++g) {
            float (*acc)[4] = (g == 0) ? accR : (g == 1) ? accI : accN;
            #pragma unroll
            for (int rh = 0; rh < 2; ++rh) {
                mma16816(acc[rh * 2 + 0], af[cur][rh], bf[cur][g] + 0);
                mma16816(acc[rh * 2 + 1], af[cur][rh], bf[cur][g] + 2);
            }
        }
    }
}

__global__ __launch_bounds__(256, 2) void qgru_mma_kernel(
    const float* __restrict__ h_in,
    const float* __restrict__ bih,
    const float* __restrict__ bhh,
    float* __restrict__ out)
{
    extern __shared__ __align__(1024) char smem[];
    const uint32_t sb = smem_u32(smem);
    const int tid  = threadIdx.x;
    const int wid  = tid >> 5;
    const int lane = tid & 31;
    const int m0 = blockIdx.y * M_TILE;
    const int n0 = blockIdx.x * N_TILE;

    const int wm = wid & 1;         // 2 M-warps: 32 rows each
    const int wn = wid >> 1;        // 4 N-warps: 16 cols each

    // ldmatrix lane geometry
    const int aRow = wm * 32 + (lane & 15);
    const uint32_t aRowB0 = (uint32_t)aRow * 128;
    const int aSw = aRow & 7;
    const int aCk = lane >> 4;
    const int bRow = wn * 16 + (lane & 7) + ((lane >> 4) << 3);
    const uint32_t bRowB = (uint32_t)bRow * 128;
    const int bSw = bRow & 7;
    const int bCk = (lane >> 3) & 1;

    float accR[4][4], accI[4][4], accNi[4][4], accNh[4][4];
    #pragma unroll
    for (int s = 0; s < 4; ++s)
        #pragma unroll
        for (int r = 0; r < 4; ++r) {
            accR[s][r] = 0.f; accI[s][r] = 0.f;
            accNi[s][r] = 0.f; accNh[s][r] = 0.f;
        }

    // ---- 3-stage pipelined main loop ----
    load_stage(sb + 0 * STAGE_B, 0, m0, n0, tid);
    CP_COMMIT();
    load_stage(sb + 1 * STAGE_B, 1, m0, n0, tid);
    CP_COMMIT();

    #pragma unroll 1
    for (int c = 0; c < CHUNKS; ++c) {
        if (c + 2 < CHUNKS) { CP_WAIT(1); } else { CP_WAIT(0); }
        __syncthreads();       // load(c) visible; compute(c-1) done by all
                               // -> stage (c+2)%3 == (c-1)%3 is free
        if (c + 2 < CHUNKS) {
            load_stage(sb + ((c + 2) % NSTAGES) * STAGE_B, c + 2, m0, n0, tid);
            CP_COMMIT();
        }
        const uint32_t stb = sb + (c % NSTAGES) * STAGE_B;
        if (c < 8)
            compute_chunk(stb, accR, accI, accNi, aRowB0, aSw, aCk, bRowB, bSw, bCk);
        else
            compute_chunk(stb, accR, accI, accNh, aRowB0, aSw, aCk, bRowB, bSw, bCk);
    }

    // ---- fused quantized GRU epilogue ----
    const int l4 = lane >> 2;
    const int lm = lane & 3;

    #pragma unroll
    for (int pos = 0; pos < 4; ++pos) {
        const int rh = pos >> 1;
        const int nh = pos & 1;
        const int col = n0 + wn * 16 + nh * 8 + lm * 2;
        const float br0 = __ldg(bih + col)     + __ldg(bhh + col);
        const float br1 = __ldg(bih + col + 1) + __ldg(bhh + col + 1);
        const float bi0 = __ldg(bih + 512 + col)     + __ldg(bhh + 512 + col);
        const float bi1 = __ldg(bih + 512 + col + 1) + __ldg(bhh + 512 + col + 1);
        const float bni0 = __ldg(bih + 1024 + col);
        const float bni1 = __ldg(bih + 1024 + col + 1);
        const float bnh0 = __ldg(bhh + 1024 + col);
        const float bnh1 = __ldg(bhh + 1024 + col + 1);

        #pragma unroll
        for (int half = 0; half < 2; ++half) {
            const int row = m0 + wm * 32 + rh * 16 + l4 + half * 8;
            const float2 hv = *reinterpret_cast<const float2*>(
                h_in + (size_t)row * KDIM + col);
            float res[2];
            #pragma unroll
            for (int e = 0; e < 2; ++e) {
                const int r = half * 2 + e;
                const float rsum = accR[pos][r] + (e ? br1 : br0);
                const float isum = accI[pos][r] + (e ? bi1 : bi0);
                const float gin  = qround(accNi[pos][r] + (e ? bni1 : bni0),
                                          Q14F, IQ14F);
                const float ghn  = qround(accNh[pos][r] + (e ? bnh1 : bnh0),
                                          Q14F, IQ14F);
                const float resetg = qsigmoid_dev(rsum);
                const float inputg = qsigmoid_dev(isum);
                const float rhn  = qround(__fmul_rn(resetg, ghn), Q15F, IQ15F);
                const float newg = qtanh_dev(rhn + gin);
                const float nh2  = qround(e ? hv.y : hv.x, Q15F, IQ15F);
                res[e] = __fadd_rn(newg,
                                   __fmul_rn(inputg, __fsub_rn(nh2, newg)));
            }
            float2 o; o.x = res[0]; o.y = res[1];
            *reinterpret_cast<float2*>(out + (size_t)row * KDIM + col) = o;
        }
    }
}

extern "C" void kernel_launch(void* const* d_in, const int* in_sizes, int n_in,
                              void* d_out, int out_size) {
    const float* x   = (const float*)d_in[0];  // [8192, 512]
    const float* h   = (const float*)d_in[1];  // [8192, 512]
    const float* wih = (const float*)d_in[2];  // [1536, 512]
    const float* whh = (const float*)d_in[3];  // [1536, 512]
    const float* bih = (const float*)d_in[4];  // [1536]
    const float* bhh = (const float*)d_in[5];  // [1536]
    float* out = (float*)d_out;                // [8192, 512]

    cvt4_kernel<<<TOT4 / 256, 256>>>(x, h, wih, whh);

    cudaFuncSetAttribute(qgru_mma_kernel,
                         cudaFuncAttributeMaxDynamicSharedMemorySize, SMEM_TOTAL);
    dim3 grid(KDIM / N_TILE, BATCH / M_TILE);  // (8, 128) = 1024 CTAs
    qgru_mma_kernel<<<grid, 256, SMEM_TOTAL>>>(h, bih, bhh, out);
}